// round 15
// baseline (speedup 1.0000x reference)
#include <cuda_runtime.h>

// Problem constants (fixed by setup_inputs)
#define M_PTS   1024
#define BATCH   2
#define NC      64
#define NCEN    (BATCH * NC)       // 128 centers
#define KS      13
#define NA      20
#define DOUT    64
#define KP      (KS * NA)          // 260 kernel positions
#define R2      0.16f              // RADIUS^2
// S = -log2(e) / (2*SIGMA) = -1.4426950408889634 / 0.16
#define S_CONST (-9.016844005556021f)
#define M2S     (18.033688011112042f)   // -2*S

#define NAG     2                  // anchor groups (blocks) per center
#define NA_BLK  (NA / NAG)         // 10 anchors per block
#define KP_BLK  (KS * NA_BLK)      // 130 kernel positions per block

#define NT      512                // 16 warps
#define NW      (NT / 32)
#define NCHUNKS (M_PTS / NT)       // 2 compaction rounds
// kps with index < KP4 have 4 workers; the rest have 3 (NT = 4*KP4 + 3*(KP_BLK-KP4))
#define KP4     (NT - 3 * KP_BLK)  // 122

__device__ __forceinline__ float ex2(float x) {
    float y;
    asm("ex2.approx.ftz.f32 %0, %1;" : "=f"(y) : "f"(x));
    return y;
}

__global__ __launch_bounds__(NT, 2)
void kp_fused_kernel(const float* __restrict__ frag,      // (M,3)
                     const float* __restrict__ clouds,    // (B,3,NC)
                     const float* __restrict__ kernels,   // (KS,NA,3) -> [KP][3]
                     const float* __restrict__ W,         // (DOUT,KS)
                     float* __restrict__ out)             // (B,DOUT,NC,NA)
{
    __shared__ float4 s_pts[M_PTS];      // {rx, ry, rz, ex2(S*|r|^2)}
    __shared__ float  s_part[4][KP_BLK]; // per-(par,kp) partial sums
    __shared__ float  s_wts[KP_BLK];
    __shared__ float  s_W[DOUT * KS];
    __shared__ int    s_wcnt[NCHUNKS][NW];

    const int tid  = threadIdx.x;
    const int lane = tid & 31;
    const int wrp  = tid >> 5;

    const int blk    = blockIdx.x;
    const int center = blk >> 1;         // / NAG
    const int ag     = blk & 1;          // anchor group
    const int bb     = center >> 6;      // / NC
    const int n      = center & 63;      // % NC

    // thread -> (local kernel position, worker index).
    // kps 0..KP4-1 get 4 workers, kps KP4..KP_BLK-1 get 3.
    const int kpl  = tid % KP_BLK;
    const int par  = tid / KP_BLK;       // 0..3 (par==3 only for kpl < KP4)
    const int npar = (kpl < KP4) ? 4 : 3;

    const int kidx = kpl / NA_BLK;              // ks index
    const int al   = kpl - kidx * NA_BLK;       // local anchor
    const int kpg  = kidx * NA + ag * NA_BLK + al;
    const float kx = kernels[3 * kpg + 0];
    const float ky = kernels[3 * kpg + 1];
    const float kz = kernels[3 * kpg + 2];

    const float cx = clouds[bb * 3 * NC + 0 * NC + n];
    const float cy = clouds[bb * 3 * NC + 1 * NC + n];
    const float cz = clouds[bb * 3 * NC + 2 * NC + n];

    // Preload conv weights into shared (overlaps with phase 1)
    for (int idx = tid; idx < DOUT * KS; idx += NT) s_W[idx] = W[idx];

    // ---------------- Phase 1: in-ball compaction (2 ballot rounds) ------------
    int base = 0;
    #pragma unroll
    for (int chunk = 0; chunk < NCHUNKS; chunk++) {
        const int i = chunk * NT + tid;
        const float rx = frag[3 * i + 0] - cx;
        const float ry = frag[3 * i + 1] - cy;
        const float rz = frag[3 * i + 2] - cz;
        const float rn2 = fmaf(rz, rz, fmaf(ry, ry, rx * rx));
        const bool pred = rn2 < R2;

        const unsigned bal = __ballot_sync(0xffffffffu, pred);
        if (lane == 0) s_wcnt[chunk][wrp] = __popc(bal);
        __syncthreads();
        int prefix = 0, total = 0;
        #pragma unroll
        for (int w = 0; w < NW; w++) {
            const int c = s_wcnt[chunk][w];   // chunk-indexed: no cross-round race
            if (w < wrp) prefix += c;
            total += c;
        }
        if (pred) {
            const int pos = base + prefix + __popc(bal & ((1u << lane) - 1u));
            s_pts[pos] = make_float4(rx, ry, rz, ex2(rn2 * S_CONST));
        }
        base += total;   // identical running total in every thread
    }
    __syncthreads();
    const int cnt = base;

    // ------- Phase 2: gaussian accumulation, npar workers per kernel position --
    {
        const float ps = fmaf(kz, kz, fmaf(ky, ky, kx * kx)) * S_CONST;

        float a0 = 0.f, a1 = 0.f, a2 = 0.f, a3 = 0.f;
        const int st1 = npar, st2 = 2 * npar, st3 = 3 * npar, st4 = 4 * npar;
        int j = par;
        for (; j + st3 < cnt; j += st4) {
            const float4 r0 = s_pts[j];
            const float4 r1 = s_pts[j + st1];
            const float4 r2 = s_pts[j + st2];
            const float4 r3 = s_pts[j + st3];
            const float d0 = fmaf(r0.z, kz, fmaf(r0.y, ky, r0.x * kx));
            const float d1 = fmaf(r1.z, kz, fmaf(r1.y, ky, r1.x * kx));
            const float d2 = fmaf(r2.z, kz, fmaf(r2.y, ky, r2.x * kx));
            const float d3 = fmaf(r3.z, kz, fmaf(r3.y, ky, r3.x * kx));
            a0 = fmaf(r0.w, ex2(fmaf(d0, M2S, ps)), a0);
            a1 = fmaf(r1.w, ex2(fmaf(d1, M2S, ps)), a1);
            a2 = fmaf(r2.w, ex2(fmaf(d2, M2S, ps)), a2);
            a3 = fmaf(r3.w, ex2(fmaf(d3, M2S, ps)), a3);
        }
        for (; j < cnt; j += st1) {
            const float4 r0 = s_pts[j];
            const float d0 = fmaf(r0.z, kz, fmaf(r0.y, ky, r0.x * kx));
            a0 = fmaf(r0.w, ex2(fmaf(d0, M2S, ps)), a0);
        }
        s_part[par][kpl] = (a0 + a1) + (a2 + a3);
        // ghost slots: kpl KP4..KP_BLK-1 have no par-3 worker
        if (tid < KP_BLK - KP4) s_part[3][KP4 + tid] = 0.f;
    }
    __syncthreads();

    // ---------------- combine partials (fixed order -> deterministic) ----------
    if (tid < KP_BLK) {
        const float s = ((s_part[0][tid] + s_part[1][tid]) +
                         (s_part[2][tid] + s_part[3][tid]));
        s_wts[tid] = __fdividef(s, (float)cnt + 1.0f);
    }
    __syncthreads();

    // ---------------- Phase 3: 1x1 SO3 conv + store (this block's anchors) -----
    // feats[b,o,n,ag*NA_BLK+al] = sum_k W[o,k] * wts[k*NA_BLK + al]
    for (int oa = tid; oa < DOUT * NA_BLK; oa += NT) {
        const int o  = oa / NA_BLK;
        const int a  = oa % NA_BLK;
        float s = 0.f;
        #pragma unroll
        for (int k = 0; k < KS; k++)
            s = fmaf(s_W[o * KS + k], s_wts[k * NA_BLK + a], s);
        out[(bb * DOUT + o) * (NC * NA) + n * NA + ag * NA_BLK + a] = s;
    }
}

extern "C" void kernel_launch(void* const* d_in, const int* in_sizes, int n_in,
                              void* d_out, int out_size) {
    const float* frag    = (const float*)d_in[0];   // (1024,3)
    const float* clouds  = (const float*)d_in[1];   // (2,3,64)
    const float* kernels = (const float*)d_in[2];   // (13,20,3)
    const float* W       = (const float*)d_in[3];   // (64,13)
    float* out = (float*)d_out;                     // (2,64,64,20)

    kp_fused_kernel<<<NCEN * NAG, NT>>>(frag, clouds, kernels, W, out);
}

// round 16
// speedup vs baseline: 1.1536x; 1.1536x over previous
#include <cuda_runtime.h>

// Problem constants (fixed by setup_inputs)
#define M_PTS   1024
#define BATCH   2
#define NC      64
#define NCEN    (BATCH * NC)       // 128 centers
#define KS      13
#define NA      20
#define DOUT    64
#define KP      (KS * NA)          // 260 kernel positions
#define R2      0.16f              // RADIUS^2
// S = -log2(e) / (2*SIGMA) = -1.4426950408889634 / 0.16
#define S_CONST (-9.016844005556021f)
#define M2S     (18.033688011112042f)   // -2*S

#define NT      1024               // one block per center, 32 warps
#define NW      (NT / 32)
// kps with index < KP4 have 4 workers; the rest have 3 (NT = 4*KP4 + 3*(KP-KP4))
#define KP4     (NT - 3 * KP)      // 244
#define MAXPAIR 513                // ceil((M_PTS+2)/2)

typedef unsigned long long u64;

__device__ __forceinline__ float ex2(float x) {
    float y;
    asm("ex2.approx.ftz.f32 %0, %1;" : "=f"(y) : "f"(x));
    return y;
}
__device__ __forceinline__ u64 pk2(float lo, float hi) {
    u64 r; asm("mov.b64 %0, {%1, %2};" : "=l"(r) : "f"(lo), "f"(hi)); return r;
}
__device__ __forceinline__ void upk2(u64 v, float& lo, float& hi) {
    asm("mov.b64 {%0, %1}, %2;" : "=f"(lo), "=f"(hi) : "l"(v));
}
__device__ __forceinline__ u64 fma2(u64 a, u64 b, u64 c) {
    u64 d; asm("fma.rn.f32x2 %0, %1, %2, %3;" : "=l"(d) : "l"(a), "l"(b), "l"(c)); return d;
}
__device__ __forceinline__ u64 mul2(u64 a, u64 b) {
    u64 d; asm("mul.rn.f32x2 %0, %1, %2;" : "=l"(d) : "l"(a), "l"(b)); return d;
}

__global__ __launch_bounds__(NT, 1)
void kp_fused_kernel(const float* __restrict__ frag,      // (M,3)
                     const float* __restrict__ clouds,    // (B,3,NC)
                     const float* __restrict__ kernels,   // (KS,NA,3) -> [KP][3]
                     const float* __restrict__ W,         // (DOUT,KS)
                     float* __restrict__ out)             // (B,DOUT,NC,NA)
{
    __shared__ float4 s_xy[MAXPAIR];     // {x0,x1,y0,y1} per point-pair
    __shared__ float4 s_zw[MAXPAIR];     // {z0,z1,w0,w1}, w = ex2(S*|r|^2)
    __shared__ float  s_part[4][KP];     // per-(par,kp) partial sums
    __shared__ float  s_wts[KP];
    __shared__ float  s_W[DOUT * KS];
    __shared__ int    s_wcnt[NW];
    __shared__ int    s_total;

    const int tid  = threadIdx.x;
    const int lane = tid & 31;
    const int wrp  = tid >> 5;

    const int center = blockIdx.x;       // b*NC + n
    const int bb     = center >> 6;      // / NC
    const int n      = center & 63;      // % NC

    // thread -> (kernel position, worker index). kps 0..KP4-1 get 4 workers,
    // kps KP4..259 get 3. Stride MUST equal the kp's worker count.
    const int kp   = tid % KP;
    const int par  = tid / KP;           // 0..3 (par==3 only for kp < KP4)
    const int npar = (kp < KP4) ? 4 : 3;

    const float kx = kernels[3 * kp + 0];
    const float ky = kernels[3 * kp + 1];
    const float kz = kernels[3 * kp + 2];

    const float cx = clouds[bb * 3 * NC + 0 * NC + n];
    const float cy = clouds[bb * 3 * NC + 1 * NC + n];
    const float cz = clouds[bb * 3 * NC + 2 * NC + n];

    // Preload conv weights into shared (overlaps with phase 1)
    for (int idx = tid; idx < DOUT * KS; idx += NT) s_W[idx] = W[idx];

    // ------- Phase 1: one-shot compaction, pair-interleaved packed layout ------
    {
        const float rx = frag[3 * tid + 0] - cx;
        const float ry = frag[3 * tid + 1] - cy;
        const float rz = frag[3 * tid + 2] - cz;
        const float rn2 = fmaf(rz, rz, fmaf(ry, ry, rx * rx));
        const bool pred = rn2 < R2;

        const unsigned bal = __ballot_sync(0xffffffffu, pred);
        if (lane == 0) s_wcnt[wrp] = __popc(bal);
        __syncthreads();
        int prefix = 0, total = 0;
        #pragma unroll
        for (int w = 0; w < NW; w++) {
            const int c = s_wcnt[w];
            if (w < wrp) prefix += c;
            total += c;
        }
        if (pred) {
            const int pos  = prefix + __popc(bal & ((1u << lane) - 1u));
            const int pair = pos >> 1;
            const int l    = pos & 1;
            float* fxy = (float*)&s_xy[pair];
            float* fzw = (float*)&s_zw[pair];
            fxy[l]     = rx;
            fxy[2 + l] = ry;
            fzw[l]     = rz;
            fzw[2 + l] = ex2(rn2 * S_CONST);
        }
        if (tid == 0) {
            // pad slots total, total+1 with zero-weight points (disjoint from
            // compaction writes which cover slots < total)
            #pragma unroll
            for (int t = 0; t < 2; t++) {
                const int pos  = total + t;
                const int pair = pos >> 1;
                const int l    = pos & 1;
                float* fxy = (float*)&s_xy[pair];
                float* fzw = (float*)&s_zw[pair];
                fxy[l] = 0.f; fxy[2 + l] = 0.f; fzw[l] = 0.f; fzw[2 + l] = 0.f;
            }
            s_total = total;
        }
        __syncthreads();
    }
    const int cnt    = s_total;
    const int npairs = (cnt + 1) >> 1;   // padded to even point count

    // ------- Phase 2: packed f32x2 gaussian accumulation (2 points / lane) -----
    {
        const float ps = fmaf(kz, kz, fmaf(ky, ky, kx * kx)) * S_CONST;
        const u64 kx2  = pk2(kx, kx);
        const u64 ky2  = pk2(ky, ky);
        const u64 kz2  = pk2(kz, kz);
        const u64 m2s2 = pk2(M2S, M2S);
        const u64 ps2  = pk2(ps, ps);

        u64 acc0 = 0ull, acc1 = 0ull;    // bitwise (0.f, 0.f)
        const int st2 = 2 * npar;
        int j = par;
        for (; j + npar < npairs; j += st2) {
            const float4 xy0 = s_xy[j];
            const float4 zw0 = s_zw[j];
            const float4 xy1 = s_xy[j + npar];
            const float4 zw1 = s_zw[j + npar];
            const u64 d0 = fma2(pk2(zw0.x, zw0.y), kz2,
                           fma2(pk2(xy0.z, xy0.w), ky2,
                           mul2(pk2(xy0.x, xy0.y), kx2)));
            const u64 d1 = fma2(pk2(zw1.x, zw1.y), kz2,
                           fma2(pk2(xy1.z, xy1.w), ky2,
                           mul2(pk2(xy1.x, xy1.y), kx2)));
            const u64 g0 = fma2(d0, m2s2, ps2);
            const u64 g1 = fma2(d1, m2s2, ps2);
            float a0, b0, a1, b1;
            upk2(g0, a0, b0);
            upk2(g1, a1, b1);
            acc0 = fma2(pk2(zw0.z, zw0.w), pk2(ex2(a0), ex2(b0)), acc0);
            acc1 = fma2(pk2(zw1.z, zw1.w), pk2(ex2(a1), ex2(b1)), acc1);
        }
        for (; j < npairs; j += npar) {
            const float4 xy0 = s_xy[j];
            const float4 zw0 = s_zw[j];
            const u64 d0 = fma2(pk2(zw0.x, zw0.y), kz2,
                           fma2(pk2(xy0.z, xy0.w), ky2,
                           mul2(pk2(xy0.x, xy0.y), kx2)));
            const u64 g0 = fma2(d0, m2s2, ps2);
            float a0, b0;
            upk2(g0, a0, b0);
            acc0 = fma2(pk2(zw0.z, zw0.w), pk2(ex2(a0), ex2(b0)), acc0);
        }
        float l0, h0, l1, h1;
        upk2(acc0, l0, h0);
        upk2(acc1, l1, h1);
        s_part[par][kp] = (l0 + h0) + (l1 + h1);
        // ghost slots: kp KP4..259 have no par-3 worker
        if (tid < KP - KP4) s_part[3][KP4 + tid] = 0.f;
    }
    __syncthreads();

    // ---------------- combine partials (fixed order -> deterministic) ----------
    if (tid < KP) {
        const float s = ((s_part[0][tid] + s_part[1][tid]) +
                         (s_part[2][tid] + s_part[3][tid]));
        s_wts[tid] = __fdividef(s, (float)cnt + 1.0f);
    }
    __syncthreads();

    // ---------------- Phase 3: 1x1 SO3 conv + store ----------------------------
    // feats[b,o,n,a] = sum_k W[o,k] * wts[k*NA + a]
    for (int oa = tid; oa < DOUT * NA; oa += NT) {
        const int o = oa / NA;
        const int a = oa % NA;
        float s = 0.f;
        #pragma unroll
        for (int k = 0; k < KS; k++)
            s = fmaf(s_W[o * KS + k], s_wts[k * NA + a], s);
        out[(bb * DOUT + o) * (NC * NA) + n * NA + a] = s;
    }
}

extern "C" void kernel_launch(void* const* d_in, const int* in_sizes, int n_in,
                              void* d_out, int out_size) {
    const float* frag    = (const float*)d_in[0];   // (1024,3)
    const float* clouds  = (const float*)d_in[1];   // (2,3,64)
    const float* kernels = (const float*)d_in[2];   // (13,20,3)
    const float* W       = (const float*)d_in[3];   // (64,13)
    float* out = (float*)d_out;                     // (2,64,64,20)

    kp_fused_kernel<<<NCEN, NT>>>(frag, clouds, kernels, W, out);
}